// round 4
// baseline (speedup 1.0000x reference)
#include <cuda_runtime.h>

#define NN   2048
#define NN2  (NN*NN)
#define DT   0.01f
#define ITERS 5

// ---------------- device scratch (no cudaMalloc allowed) ----------------
__device__ float g_ku[NN2];
__device__ float g_kv[NN2];
__device__ float g_bu[NN2];
__device__ float g_bv[NN2];
__device__ float g_b [NN2];
__device__ float g_pB[NN2];
__device__ float g_r1[1024*1024];
__device__ float g_r2[512*512];
__device__ float g_r3[256*256];
__device__ float g_r4[128*128];
__device__ float g_r5[64*64];
__device__ float g_wa[1024*1024];
__device__ float g_wb[1024*1024];

// ---------------- helpers ----------------
__device__ __forceinline__ float ldz(const float* __restrict__ a, int i, int j) {
    return (i >= 0 && i < NN && j >= 0 && j < NN) ? a[i*NN + j] : 0.f;
}
__device__ __forceinline__ float lde(const float* __restrict__ a, int i, int j) {
    i = max(0, min(NN-1, i)); j = max(0, min(NN-1, j));
    return a[i*NN + j];
}
// pointwise Petrov-Galerkin coefficient (DX=DY=1)
__device__ __forceinline__ float kcoef(float uc, float vc, float AD2,
                                       float ADx, float ADy, float k1v) {
    float num = 0.25f * fabsf(0.5f * (fabsf(uc) + fabsf(vc)) * AD2);
    float den = 0.001f + 0.5f * (fabsf(ADx) + fabsf(ADy));
    return fminf(num / den, k1v);
}

// ---------------- k-coefficient pass (used for (u,v) and (b_u,b_v)) ----------------
__global__ void kK(const float* __restrict__ a, const float* __restrict__ b,
                   const float* __restrict__ k1,
                   float* __restrict__ kou, float* __restrict__ kov) {
    int j = blockIdx.x*blockDim.x + threadIdx.x;
    int i = blockIdx.y*blockDim.y + threadIdx.y;
    int ij = i*NN + j;
    float ac = a[ij], bc = b[ij];
    float an = ldz(a,i-1,j), as_ = ldz(a,i+1,j), aw = ldz(a,i,j-1), ae = ldz(a,i,j+1);
    float bn = ldz(b,i-1,j), bs_ = ldz(b,i+1,j), bw = ldz(b,i,j-1), be = ldz(b,i,j+1);
    float ADx_a = 0.5f*(ae - aw), ADy_a = 0.5f*(as_ - an), AD2_a = an+as_+aw+ae - 4.f*ac;
    float ADx_b = 0.5f*(be - bw), ADy_b = 0.5f*(bs_ - bn), AD2_b = bn+bs_+bw+be - 4.f*bc;
    float k1v = k1[ij];
    kou[ij] = kcoef(ac, bc, AD2_a, ADx_a, ADy_a, k1v);
    kov[ij] = kcoef(ac, bc, AD2_b, ADx_b, ADy_b, k1v);
}

// ---------------- predictor: b_u, b_v ----------------
__global__ void kA2(const float* __restrict__ u, const float* __restrict__ v,
                    const float* __restrict__ ku, const float* __restrict__ kv,
                    const float* __restrict__ p,
                    float* __restrict__ bu, float* __restrict__ bv) {
    int j = blockIdx.x*blockDim.x + threadIdx.x;
    int i = blockIdx.y*blockDim.y + threadIdx.y;
    int ij = i*NN + j;
    float uc = u[ij], vc = v[ij];
    float un = ldz(u,i-1,j), us_ = ldz(u,i+1,j), uw = ldz(u,i,j-1), ue = ldz(u,i,j+1);
    float vn = ldz(v,i-1,j), vs_ = ldz(v,i+1,j), vw = ldz(v,i,j-1), ve = ldz(v,i,j+1);
    float ADx_u = 0.5f*(ue - uw), ADy_u = 0.5f*(us_ - un), AD2_u = un+us_+uw+ue - 4.f*uc;
    float ADx_v = 0.5f*(ve - vw), ADy_v = 0.5f*(vs_ - vn), AD2_v = vn+vs_+vw+ve - 4.f*vc;
    float kuc = ku[ij];
    float kun = ldz(ku,i-1,j), kus = ldz(ku,i+1,j), kuw = ldz(ku,i,j-1), kue = ldz(ku,i,j+1);
    float kvc = kv[ij];
    float kvn = ldz(kv,i-1,j), kvs = ldz(kv,i+1,j), kvw = ldz(kv,i,j-1), kve = ldz(kv,i,j+1);
    float kx = 1.5f*( kuc*AD2_u
                    + (un*kun + us_*kus + uw*kuw + ue*kue - 4.f*uc*kuc)
                    - uc*(kun + kus + kuw + kue - 4.f*kuc) );
    float ky = 1.5f*( kvc*AD2_v
                    + (vn*kvn + vs_*kvs + vw*kvw + ve*kve - 4.f*vc*kvc)
                    - vc*(kvn + kvs + kvw + kve - 4.f*kvc) );
    float Grapx = DT*0.5f*(lde(p,i,j+1) - lde(p,i,j-1));
    float Grapy = DT*0.5f*(lde(p,i+1,j) - lde(p,i-1,j));
    bu[ij] = uc + 0.5f*DT*(kx - uc*ADx_u - vc*ADy_u) - Grapx;
    bv[ij] = vc + 0.5f*DT*(ky - uc*ADx_v - vc*ADy_v) - Grapy;
}

// ---------------- corrector: u*, v* ----------------
__global__ void kB2(const float* __restrict__ u,  const float* __restrict__ v,
                    const float* __restrict__ bu, const float* __restrict__ bv,
                    const float* __restrict__ ku, const float* __restrict__ kv,
                    const float* __restrict__ p,
                    const float* __restrict__ Fx, const float* __restrict__ Fy,
                    float* __restrict__ us, float* __restrict__ vs) {
    int j = blockIdx.x*blockDim.x + threadIdx.x;
    int i = blockIdx.y*blockDim.y + threadIdx.y;
    int ij = i*NN + j;
    float uc = u[ij], vc = v[ij];
    float buc = bu[ij], bvc = bv[ij];
    float bun = ldz(bu,i-1,j), bus = ldz(bu,i+1,j), buw = ldz(bu,i,j-1), bue = ldz(bu,i,j+1);
    float bvn = ldz(bv,i-1,j), bvs = ldz(bv,i+1,j), bvw = ldz(bv,i,j-1), bve = ldz(bv,i,j+1);
    float ADx_bu = 0.5f*(bue - buw), ADy_bu = 0.5f*(bus - bun), AD2_bu = bun+bus+buw+bue - 4.f*buc;
    float ADx_bv = 0.5f*(bve - bvw), ADy_bv = 0.5f*(bvs - bvn), AD2_bv = bvn+bvs+bvw+bve - 4.f*bvc;
    float kuc = ku[ij];
    float kun = ldz(ku,i-1,j), kus = ldz(ku,i+1,j), kuw = ldz(ku,i,j-1), kue = ldz(ku,i,j+1);
    float kvc = kv[ij];
    float kvn = ldz(kv,i-1,j), kvs = ldz(kv,i+1,j), kvw = ldz(kv,i,j-1), kve = ldz(kv,i,j+1);
    // product term uses ORIGINAL velocities (torch closes over global pads)
    float un = ldz(u,i-1,j), us_ = ldz(u,i+1,j), uw = ldz(u,i,j-1), ue = ldz(u,i,j+1);
    float vn = ldz(v,i-1,j), vs_ = ldz(v,i+1,j), vw = ldz(v,i,j-1), ve = ldz(v,i,j+1);
    float kx = 1.5f*( kuc*AD2_bu
                    + (un*kun + us_*kus + uw*kuw + ue*kue - 4.f*uc*kuc)
                    - buc*(kun + kus + kuw + kue - 4.f*kuc) );
    float ky = 1.5f*( kvc*AD2_bv
                    + (vn*kvn + vs_*kvs + vw*kvw + ve*kve - 4.f*vc*kvc)
                    - bvc*(kvn + kvs + kvw + kve - 4.f*kvc) );
    float Grapx = DT*0.5f*(lde(p,i,j+1) - lde(p,i,j-1));
    float Grapy = DT*0.5f*(lde(p,i+1,j) - lde(p,i-1,j));
    us[ij] = uc + DT*(kx - buc*ADx_bu - bvc*ADy_bu) - Grapx - Fx[ij]*DT;
    vs[ij] = vc + DT*(ky - buc*ADx_bv - bvc*ADy_bv) - Grapy - Fy[ij]*DT;
}

// ---------------- MG right-hand side ----------------
__global__ void kMGb(const float* __restrict__ us, const float* __restrict__ vs,
                     float* __restrict__ b) {
    int j = blockIdx.x*blockDim.x + threadIdx.x;
    int i = blockIdx.y*blockDim.y + threadIdx.y;
    int ij = i*NN + j;
    float div = 0.5f*(ldz(us,i,j+1) - ldz(us,i,j-1))
              + 0.5f*(ldz(vs,i+1,j) - ldz(vs,i-1,j));
    b[ij] = -div / DT;
}

// ---------------- residual fused with first restriction (2048 -> 1024) ----------------
__global__ void kResRestrict(const float* __restrict__ p, const float* __restrict__ b,
                             float* __restrict__ r1) {
    int J = blockIdx.x*blockDim.x + threadIdx.x;
    int I = blockIdx.y*blockDim.y + threadIdx.y;
    float acc = 0.f;
    #pragma unroll
    for (int di = 0; di < 2; di++)
    #pragma unroll
    for (int dj = 0; dj < 2; dj++) {
        int i = 2*I + di, j = 2*J + dj;
        float s = lde(p,i-1,j) + lde(p,i+1,j) + lde(p,i,j-1) + lde(p,i,j+1);
        acc += s - 4.f*p[i*NN + j] - b[i*NN + j];
    }
    r1[I*1024 + J] = 0.25f*acc;
}

// ---------------- generic 2x restriction ----------------
__global__ void kRestrict(const float* __restrict__ in, float* __restrict__ out, int sout) {
    int J = blockIdx.x*blockDim.x + threadIdx.x;
    int I = blockIdx.y*blockDim.y + threadIdx.y;
    if (I >= sout || J >= sout) return;
    int sin = 2*sout;
    const float* s = in + (2*I)*sin + 2*J;
    out[I*sout + J] = 0.25f*(s[0] + s[1] + s[sin] + s[sin+1]);
}

// smooth (w + lap0(w)/4 - r/4 == (sum4 - r)/4) then 2x nearest upsample
__device__ __forceinline__ void smoothUp(const float* win, const float* r,
                                         float* wout, int s, int t) {
    for (int idx = t; idx < s*s; idx += 1024) {
        int I = idx / s, J = idx % s;
        float sum = 0.f;
        if (I > 0)     sum += win[idx - s];
        if (I < s - 1) sum += win[idx + s];
        if (J > 0)     sum += win[idx - 1];
        if (J < s - 1) sum += win[idx + 1];
        float ws = 0.25f*(sum - r[idx]);
        float* o = wout + (2*I)*(2*s) + 2*J;
        o[0] = ws; o[1] = ws; o[2*s] = ws; o[2*s + 1] = ws;
    }
}

// ---------------- coarse pyramid: restrict 64->2, upsweep 2->128, one block ----------------
__global__ void kCoarse(const float* __restrict__ r5, float* __restrict__ wout,
                        float* __restrict__ out_r, int writeR) {
    __shared__ float r6[1024], r7[256], r8[64], r9[16], r10[4];
    __shared__ float wA[4096], wB[4096];
    int t = threadIdx.x;
    { int I = t >> 5, J = t & 31;
      const float* s = r5 + (2*I)*64 + 2*J;
      r6[t] = 0.25f*(s[0] + s[1] + s[64] + s[65]); }
    __syncthreads();
    if (t < 256) { int I = t >> 4, J = t & 15; const float* s = r6 + (2*I)*32 + 2*J;
                   r7[t] = 0.25f*(s[0] + s[1] + s[32] + s[33]); }
    __syncthreads();
    if (t < 64)  { int I = t >> 3, J = t & 7;  const float* s = r7 + (2*I)*16 + 2*J;
                   r8[t] = 0.25f*(s[0] + s[1] + s[16] + s[17]); }
    __syncthreads();
    if (t < 16)  { int I = t >> 2, J = t & 3;  const float* s = r8 + (2*I)*8 + 2*J;
                   r9[t] = 0.25f*(s[0] + s[1] + s[8] + s[9]); }
    __syncthreads();
    if (t < 4)   { int I = t >> 1, J = t & 1;  const float* s = r9 + (2*I)*4 + 2*J;
                   r10[t] = 0.25f*(s[0] + s[1] + s[4] + s[5]); }
    __syncthreads();
    if (writeR && t < 4) out_r[t] = r10[t];
    // i=10: w=0 -> wsm = -r10/4, upsample to 4x4
    if (t < 4) { int I = t >> 1, J = t & 1; float ws = -0.25f*r10[t];
                 float* o = wA + (2*I)*4 + 2*J; o[0] = ws; o[1] = ws; o[4] = ws; o[5] = ws; }
    __syncthreads();
    smoothUp(wA, r9, wB, 4,  t); __syncthreads();
    smoothUp(wB, r8, wA, 8,  t); __syncthreads();
    smoothUp(wA, r7, wB, 16, t); __syncthreads();
    smoothUp(wB, r6, wA, 32, t); __syncthreads();
    smoothUp(wA, r5, wout, 64, t);   // -> 128x128 in global
}

// ---------------- generic smooth+upsample for mid levels ----------------
__global__ void kUp(const float* __restrict__ win, const float* __restrict__ r,
                    float* __restrict__ wout, int s) {
    int J = blockIdx.x*blockDim.x + threadIdx.x;
    int I = blockIdx.y*blockDim.y + threadIdx.y;
    if (I >= s || J >= s) return;
    int id = I*s + J;
    float sum = 0.f;
    if (I > 0)     sum += win[id - s];
    if (I < s - 1) sum += win[id + s];
    if (J > 0)     sum += win[id - 1];
    if (J < s - 1) sum += win[id + 1];
    float ws = 0.25f*(sum - r[id]);
    float* o = wout + (2*I)*(2*s) + 2*J;
    o[0] = ws; o[1] = ws; o[2*s] = ws; o[2*s + 1] = ws;
}

// ---------------- fused final prolongation (1024->2048) + p correction + Jacobi ----------------
// p_new = 0.25*( sum4_edge(p - w2048) - b ), w2048 from smoothed w1024 via smem tile
__global__ void kPUpdate(const float* __restrict__ pin, const float* __restrict__ w1024,
                         const float* __restrict__ r1, const float* __restrict__ b,
                         float* __restrict__ pout, float* __restrict__ out_w, int writeW) {
    __shared__ float wsm[18][19];
    int tx = threadIdx.x, ty = threadIdx.y;
    int bi = blockIdx.y, bj = blockIdx.x;
    int Ib = bi*16 - 1, Jb = bj*16 - 1;
    int t = ty*32 + tx;
    if (t < 324) {
        int a = t / 18, c = t % 18;
        int Ic = Ib + a, Jc = Jb + c;
        float val = 0.f;
        if (Ic >= 0 && Ic < 1024 && Jc >= 0 && Jc < 1024) {
            int id = Ic*1024 + Jc;
            float sum = 0.f;
            if (Ic > 0)    sum += w1024[id - 1024];
            if (Ic < 1023) sum += w1024[id + 1024];
            if (Jc > 0)    sum += w1024[id - 1];
            if (Jc < 1023) sum += w1024[id + 1];
            val = 0.25f*(sum - r1[id]);
        }
        wsm[a][c] = val;
    }
    __syncthreads();
    int i = bi*32 + ty, j = bj*32 + tx;
    auto pp = [&](int a, int c) -> float {
        a = max(0, min(NN-1, a)); c = max(0, min(NN-1, c));
        return pin[a*NN + c] - wsm[(a >> 1) - Ib][(c >> 1) - Jb];
    };
    float pn = 0.25f*( pp(i-1,j) + pp(i+1,j) + pp(i,j-1) + pp(i,j+1) - b[i*NN + j] );
    pout[i*NN + j] = pn;
    if (writeW) out_w[i*NN + j] = wsm[(i >> 1) - Ib][(j >> 1) - Jb];
}

// ---------------- final velocity correction ----------------
__global__ void kFinalUV(const float* __restrict__ p,
                         float* __restrict__ u, float* __restrict__ v) {
    int j = blockIdx.x*blockDim.x + threadIdx.x;
    int i = blockIdx.y*blockDim.y + threadIdx.y;
    int ij = i*NN + j;
    float gx = DT*0.5f*(lde(p,i,j+1) - lde(p,i,j-1));
    float gy = DT*0.5f*(lde(p,i+1,j) - lde(p,i-1,j));
    u[ij] -= gx;
    v[ij] -= gy;
}

extern "C" void kernel_launch(void* const* d_in, const int* in_sizes, int n_in,
                              void* d_out, int out_size) {
    (void)in_sizes; (void)n_in; (void)out_size;
    const float* u  = (const float*)d_in[0];
    const float* v  = (const float*)d_in[1];
    const float* p  = (const float*)d_in[2];
    const float* Fx = (const float*)d_in[3];
    const float* Fy = (const float*)d_in[4];
    const float* k1 = (const float*)d_in[5];
    // outputs: u, v, p, w (2048^2 each), r (2x2) — reference return order
    float* out   = (float*)d_out;
    float* out_u = out;
    float* out_v = out + (size_t)NN2;
    float* out_p = out + 2*(size_t)NN2;
    float* out_w = out + 3*(size_t)NN2;
    float* out_r = out + 4*(size_t)NN2;

    float *ku, *kv, *bu, *bv, *bb, *pB, *r1, *r2, *r3, *r4, *r5, *wa, *wb;
    cudaGetSymbolAddress((void**)&ku, g_ku);
    cudaGetSymbolAddress((void**)&kv, g_kv);
    cudaGetSymbolAddress((void**)&bu, g_bu);
    cudaGetSymbolAddress((void**)&bv, g_bv);
    cudaGetSymbolAddress((void**)&bb, g_b);
    cudaGetSymbolAddress((void**)&pB, g_pB);
    cudaGetSymbolAddress((void**)&r1, g_r1);
    cudaGetSymbolAddress((void**)&r2, g_r2);
    cudaGetSymbolAddress((void**)&r3, g_r3);
    cudaGetSymbolAddress((void**)&r4, g_r4);
    cudaGetSymbolAddress((void**)&r5, g_r5);
    cudaGetSymbolAddress((void**)&wa, g_wa);
    cudaGetSymbolAddress((void**)&wb, g_wb);

    dim3 blk(32, 8);
    dim3 grd(NN/32, NN/8);

    // momentum predictor / corrector
    kK <<<grd, blk>>>(u, v, k1, ku, kv);
    kA2<<<grd, blk>>>(u, v, ku, kv, p, bu, bv);
    kK <<<grd, blk>>>(bu, bv, k1, ku, kv);
    kB2<<<grd, blk>>>(u, v, bu, bv, ku, kv, p, Fx, Fy, out_u, out_v);
    kMGb<<<grd, blk>>>(out_u, out_v, bb);

    // p ping-pong: pB -> out_p -> pB -> ... ends in out_p after 5 iters
    cudaMemcpyAsync(pB, p, (size_t)NN2*sizeof(float), cudaMemcpyDeviceToDevice);

    for (int it = 0; it < ITERS; ++it) {
        const float* pin = (it & 1) ? (const float*)out_p : (const float*)pB;
        float*       pout = (it & 1) ? pB : out_p;
        int last = (it == ITERS - 1);
        kResRestrict<<<dim3(1024/32, 1024/8), blk>>>(pin, bb, r1);
        kRestrict<<<dim3(512/32, 512/8), blk>>>(r1, r2, 512);
        kRestrict<<<dim3(256/32, 256/8), blk>>>(r2, r3, 256);
        kRestrict<<<dim3(128/32, 128/8), blk>>>(r3, r4, 128);
        kRestrict<<<dim3(64/32,  64/8),  blk>>>(r4, r5, 64);
        kCoarse<<<1, 1024>>>(r5, wa, out_r, last);        // -> 128^2
        kUp<<<dim3(128/32, 128/8), blk>>>(wa, r4, wb, 128); // -> 256^2
        kUp<<<dim3(256/32, 256/8), blk>>>(wb, r3, wa, 256); // -> 512^2
        kUp<<<dim3(512/32, 512/8), blk>>>(wa, r2, wb, 512); // -> 1024^2
        kPUpdate<<<dim3(64, 64), dim3(32, 32)>>>(pin, wb, r1, bb, pout, out_w, last);
    }

    kFinalUV<<<grd, blk>>>(out_p, out_u, out_v);
}